// round 11
// baseline (speedup 1.0000x reference)
#include <cuda_runtime.h>
#include <cuda_fp16.h>
#include <cstdint>

#define BATCH   4
#define DDIM    256
#define NPTS    4096
#define MSTRIDE 4097
#define MARGIN_F 0.5f
#define MAXDIST_F 10000.0f
#define BIG_F 1000000000.0f

// ---------------- scratch ----------------
__device__ __half g_negh[(size_t)BATCH * NPTS * NPTS];        // 128 MiB
__device__ float g_pos0[BATCH][NPTS];
__device__ float g_pos1[BATCH][NPTS];
__device__ float g_mn0[BATCH][NPTS];
__device__ float g_mn1[BATCH][NPTS];
// fp16 operands, (b, d, n) layout (K-major rows of n)
__device__ __half g_f0[(size_t)BATCH * DDIM * NPTS];
__device__ __half g_f1[(size_t)BATCH * DDIM * NPTS];
__device__ float g_psum[64], g_pcnt[64], g_php[64], g_phn[64];

// ---------------- ptx helpers ----------------
#define LDSM_T4(r0,r1,r2,r3, addr)                                              \
    asm volatile("ldmatrix.sync.aligned.m8n8.x4.trans.shared.b16 "              \
                 "{%0,%1,%2,%3}, [%4];"                                         \
                 : "=r"(r0), "=r"(r1), "=r"(r2), "=r"(r3) : "r"(addr))

#define MMA16816(d, a, b0, b1)                                                  \
    asm volatile("mma.sync.aligned.m16n8k16.row.col.f32.f16.f16.f32 "           \
                 "{%0,%1,%2,%3},{%4,%5,%6,%7},{%8,%9},{%0,%1,%2,%3};"           \
                 : "+f"(d[0]), "+f"(d[1]), "+f"(d[2]), "+f"(d[3])               \
                 : "r"(a[0]), "r"(a[1]), "r"(a[2]), "r"(a[3]),                  \
                   "r"(b0), "r"(b1))

#define CP_ASYNC16(sm, gm)                                                      \
    asm volatile("cp.async.cg.shared.global [%0], [%1], 16;" :: "r"(sm), "l"(gm))
#define CP_ASYNC4(sm, gm)                                                       \
    asm volatile("cp.async.ca.shared.global [%0], [%1], 4;" :: "r"(sm), "l"(gm))
#define CP_COMMIT()  asm volatile("cp.async.commit_group;")
#define CP_WAIT1()   asm volatile("cp.async.wait_group 1;")
#define CP_WAIT0()   asm volatile("cp.async.wait_group 0;")

// ---------------- init ----------------
__global__ void init_kernel() {
    int idx = blockIdx.x * blockDim.x + threadIdx.x;
    if (idx < BATCH * NPTS) {
        ((float*)g_pos0)[idx] = 0.0f;
        ((float*)g_pos1)[idx] = 0.0f;
        ((float*)g_mn0)[idx]  = BIG_F;
        ((float*)g_mn1)[idx]  = BIG_F;
    }
}

// ---------------- prep: fp32 -> fp16, same (b,d,n) layout ----------------
__global__ __launch_bounds__(256)
void prep_kernel(const float* __restrict__ d0, const float* __restrict__ d1) {
    size_t i = ((size_t)blockIdx.x * 256 + threadIdx.x) * 4;
    float4 v0 = *(const float4*)(d0 + i);
    float4 v1 = *(const float4*)(d1 + i);
    __half2 a0 = __floats2half2_rn(v0.x, v0.y);
    __half2 a1 = __floats2half2_rn(v0.z, v0.w);
    __half2 b0 = __floats2half2_rn(v1.x, v1.y);
    __half2 b1 = __floats2half2_rn(v1.z, v1.w);
    *(uint2*)(g_f0 + i) = make_uint2(*(uint32_t*)&a0, *(uint32_t*)&a1);
    *(uint2*)(g_f1 + i) = make_uint2(*(uint32_t*)&b0, *(uint32_t*)&b1);
}

// ---------------------------------------------------------------------------
// pass1: fp16 HMMA GEMM K=256, tile 128x128, 8 warps (64x32), BK=16,
// 3-stage cp.async pipeline. mat (ov) tile prefetched to smem DURING the MMA
// loop via 4B cp.async (MSTRIDE=4097 -> rows only 4B aligned).
// Fused epilogue: dist, mask row/col max atomics, fp16 neg store.
// ---------------------------------------------------------------------------
#define LDA 136
#define NCH 16    // 256 / 16
#define MROW 132  // mat smem row stride (floats)
#define SM_AS 0
#define SM_BS 13056
#define SM_MV 26112
#define P1_SMEM (26112 + 128 * MROW * 4)   // 93696

__global__ __launch_bounds__(256, 2)
void pass1_kernel(const float* __restrict__ mat) {
    extern __shared__ char smem_raw[];
    __half (*As)[16][LDA] = (__half(*)[16][LDA])(smem_raw + SM_AS);
    __half (*Bs)[16][LDA] = (__half(*)[16][LDA])(smem_raw + SM_BS);
    float*  Ms            = (float*)(smem_raw + SM_MV);

    const int b  = blockIdx.z;
    const int i0 = blockIdx.y * 128;
    const int j0 = blockIdx.x * 128;

    const int tid = threadIdx.x;
    const int w   = tid >> 5;
    const int l   = tid & 31;
    const int m0w = (w & 1) * 64;
    const int n0w = (w >> 1) * 32;

    const __half* Ag0 = g_f0 + (size_t)b * DDIM * NPTS;
    const __half* Bg0 = g_f1 + (size_t)b * DDIM * NPTS;
    const float*  Mb  = mat + (size_t)b * MSTRIDE * MSTRIDE;

    const int lrow = tid >> 4;          // 0..15
    const int lcol = (tid & 15) * 8;    // half elems
    const int mrow = tid >> 5;          // 0..7 (row within 8-row mat chunk)
    const int mcol = (tid & 31) * 4;    // 4 floats per thread

    auto load_stage = [&](int kc) {
        int st = kc % 3;
        int kk = kc * 16;
        const __half* Ag = Ag0 + (size_t)(kk + lrow) * NPTS + i0 + lcol;
        const __half* Bg = Bg0 + (size_t)(kk + lrow) * NPTS + j0 + lcol;
        uint32_t sa = (uint32_t)__cvta_generic_to_shared(&As[st][lrow][lcol]);
        uint32_t sb = (uint32_t)__cvta_generic_to_shared(&Bs[st][lrow][lcol]);
        CP_ASYNC16(sa, Ag);
        CP_ASYNC16(sb, Bg);
        // mat chunk: rows kc*8 .. kc*8+7 of the 128x128 ov tile
        {
            int r = kc * 8 + mrow;
            const float* src = Mb + (size_t)(i0 + r) * MSTRIDE + j0 + mcol;
            uint32_t dst = (uint32_t)__cvta_generic_to_shared(&Ms[r * MROW + mcol]);
#pragma unroll
            for (int e = 0; e < 4; e++)
                CP_ASYNC4(dst + 4 * e, src + e);
        }
        CP_COMMIT();
    };

    float acc[4][4][4];
#pragma unroll
    for (int mi = 0; mi < 4; mi++)
#pragma unroll
        for (int nj = 0; nj < 4; nj++)
#pragma unroll
            for (int r = 0; r < 4; r++) acc[mi][nj][r] = 0.0f;

    const int a_row = ((l >> 4) << 3) + (l & 7);
    const int a_col = ((l >> 3) & 1) * 8;
    const int b_row = (((l >> 3) & 1) << 3) + (l & 7);
    const int b_col = (l >> 4) * 8;

    load_stage(0);
    load_stage(1);

    for (int kc = 0; kc < NCH; kc++) {
        if (kc + 1 < NCH) { CP_WAIT1(); } else { CP_WAIT0(); }
        __syncthreads();
        if (kc + 2 < NCH) load_stage(kc + 2);

        const int st = kc % 3;
        uint32_t a[4][4];
#pragma unroll
        for (int mi = 0; mi < 4; mi++) {
            uint32_t addr = (uint32_t)__cvta_generic_to_shared(
                &As[st][a_row][m0w + mi * 16 + a_col]);
            LDSM_T4(a[mi][0], a[mi][1], a[mi][2], a[mi][3], addr);
        }
        uint32_t bq[2][4];
#pragma unroll
        for (int nb = 0; nb < 2; nb++) {
            uint32_t addr = (uint32_t)__cvta_generic_to_shared(
                &Bs[st][b_row][n0w + nb * 16 + b_col]);
            LDSM_T4(bq[nb][0], bq[nb][1], bq[nb][2], bq[nb][3], addr);
        }
#pragma unroll
        for (int mi = 0; mi < 4; mi++)
#pragma unroll
            for (int nj = 0; nj < 4; nj++)
                MMA16816(acc[mi][nj], a[mi], bq[nj >> 1][(nj & 1) * 2],
                         bq[nj >> 1][(nj & 1) * 2 + 1]);
    }

    // ---- epilogue (ov from smem) ----
    __half* negbase = g_negh + (size_t)b * NPTS * NPTS;

    float cmax[4][2];
#pragma unroll
    for (int nj = 0; nj < 4; nj++) { cmax[nj][0] = 0.0f; cmax[nj][1] = 0.0f; }

#pragma unroll
    for (int mi = 0; mi < 4; mi++) {
#pragma unroll
        for (int h = 0; h < 2; h++) {
            const int rl = m0w + mi * 16 + (l >> 2) + h * 8;
            const int r  = i0 + rl;
            __half* Nr = negbase + (size_t)r * NPTS;
            float rm = 0.0f;
#pragma unroll
            for (int nj = 0; nj < 4; nj++) {
                const int cl = n0w + nj * 8 + (l & 3) * 2;
                const int cb = j0 + cl;
                float v0 = acc[mi][nj][h * 2 + 0];
                float v1 = acc[mi][nj][h * 2 + 1];
                float dA = fmaf(-2.0f, v0, 2.0f);
                float dB = fmaf(-2.0f, v1, 2.0f);
                float2 ov = *(const float2*)&Ms[rl * MROW + cl];
                if (ov.x > 0.3f) { rm = fmaxf(rm, dA); cmax[nj][0] = fmaxf(cmax[nj][0], dA); }
                if (ov.y > 0.3f) { rm = fmaxf(rm, dB); cmax[nj][1] = fmaxf(cmax[nj][1], dB); }
                float nA = (ov.x <= 0.0f) ? dA : MAXDIST_F;
                float nB = (ov.y <= 0.0f) ? dB : MAXDIST_F;
                *(__half2*)(Nr + cb) = __floats2half2_rn(nA, nB);
            }
            rm = fmaxf(rm, __shfl_xor_sync(0xffffffffu, rm, 1));
            rm = fmaxf(rm, __shfl_xor_sync(0xffffffffu, rm, 2));
            if ((l & 3) == 0)
                atomicMax((int*)&g_pos0[b][r], __float_as_int(rm));
        }
    }
#pragma unroll
    for (int nj = 0; nj < 4; nj++) {
#pragma unroll
        for (int p = 0; p < 2; p++) {
            float cm = cmax[nj][p];
            cm = fmaxf(cm, __shfl_xor_sync(0xffffffffu, cm, 4));
            cm = fmaxf(cm, __shfl_xor_sync(0xffffffffu, cm, 8));
            cm = fmaxf(cm, __shfl_xor_sync(0xffffffffu, cm, 16));
            if (l < 4)
                atomicMax((int*)&g_pos1[b][j0 + n0w + nj * 8 + (l & 3) * 2 + p],
                          __float_as_int(cm));
        }
    }
}

// ---------------------------------------------------------------------------
// pass2: masked min on fp16 neg; 128 rows x 256 cols per block,
// 16 cols/thread, half2 SIMD throughout.
// ---------------------------------------------------------------------------
__global__ __launch_bounds__(256)
void pass2_kernel() {
    const int b  = blockIdx.z;
    const int i0 = blockIdx.y * 128;
    const int j0 = blockIdx.x * 256;

    const int tid = threadIdx.x;
    const int tx = tid & 15;      // 16 threads x 16 cols = 256 cols
    const int ty = tid >> 4;      // 16 groups x 8 rows = 128 rows

    __shared__ __half2 cbuf[16][128];

    const __half* negbase = g_negh + (size_t)b * NPTS * NPTS;
    const __half2 one2 = __float2half2_rn(1.0f);
    const __half2 big2 = __float2half2_rn(30000.0f);
    const __half2 mar2 = __float2half2_rn(MARGIN_F);

    // column window bounds (8 half2 pairs covering 16 cols)
    __half2 p1lo[8], p1hi[8];
#pragma unroll
    for (int c2 = 0; c2 < 8; c2++) {
        float a = g_pos1[b][j0 + tx * 16 + 2 * c2];
        float c = g_pos1[b][j0 + tx * 16 + 2 * c2 + 1];
        p1lo[c2] = __floats2half2_rn(a, c);
        p1hi[c2] = __hadd2(p1lo[c2], mar2);
    }

    __half2 cmin2[8];
#pragma unroll
    for (int c2 = 0; c2 < 8; c2++) cmin2[c2] = big2;

#pragma unroll
    for (int r = 0; r < 8; r++) {
        const int i = i0 + ty * 8 + r;
        const float p0 = g_pos0[b][i];
        const __half2 p02  = __float2half2_rn(p0);
        const __half2 phi2 = __float2half2_rn(p0 + MARGIN_F);
        const __half* Nr = negbase + (size_t)i * NPTS + j0 + tx * 16;
        float4 raw0 = *(const float4*)Nr;
        float4 raw1 = *(const float4*)(Nr + 8);
        __half2 v[8];
        v[0] = *(__half2*)&raw0.x; v[1] = *(__half2*)&raw0.y;
        v[2] = *(__half2*)&raw0.z; v[3] = *(__half2*)&raw0.w;
        v[4] = *(__half2*)&raw1.x; v[5] = *(__half2*)&raw1.y;
        v[6] = *(__half2*)&raw1.z; v[7] = *(__half2*)&raw1.w;

        __half2 rmin2 = big2;
#pragma unroll
        for (int c2 = 0; c2 < 8; c2++) {
            __half2 ok = __hmul2(__hgt2(v[c2], p02), __hlt2(v[c2], phi2));
            rmin2 = __hmin2(rmin2, __hfma2(__hsub2(one2, ok), big2, v[c2]));

            __half2 okc = __hmul2(__hgt2(v[c2], p1lo[c2]), __hlt2(v[c2], p1hi[c2]));
            cmin2[c2] = __hmin2(cmin2[c2], __hfma2(__hsub2(one2, okc), big2, v[c2]));
        }
        // row min: reduce over the 16 tx lanes
        float m = fminf(__low2float(rmin2), __high2float(rmin2));
#pragma unroll
        for (int s = 8; s > 0; s >>= 1)
            m = fminf(m, __shfl_xor_sync(0xffffffffu, m, s));
        if (tx == 0) {
            float mv = (m < 5000.0f) ? m : BIG_F;
            atomicMin((int*)&g_mn0[b][i], __float_as_int(mv));
        }
    }

    // col min via smem (half2 lanes)
#pragma unroll
    for (int c2 = 0; c2 < 8; c2++)
        cbuf[ty][tx * 8 + c2] = cmin2[c2];
    __syncthreads();
    if (tid < 128) {
        __half2 m2 = big2;
#pragma unroll
        for (int rr = 0; rr < 16; rr++)
            m2 = __hmin2(m2, cbuf[rr][tid]);
        float mlo = __low2float(m2), mhi = __high2float(m2);
        float vlo = (mlo < 5000.0f) ? mlo : BIG_F;
        float vhi = (mhi < 5000.0f) ? mhi : BIG_F;
        atomicMin((int*)&g_mn1[b][j0 + 2 * tid],     __float_as_int(vlo));
        atomicMin((int*)&g_mn1[b][j0 + 2 * tid + 1], __float_as_int(vhi));
    }
}

// ---------------------------------------------------------------------------
// final reduction: 64-block partial + tiny finalize
// ---------------------------------------------------------------------------
__global__ __launch_bounds__(256)
void partial_kernel() {
    const int tid = threadIdx.x;
    float sum = 0.0f, cnt = 0.0f, hp = -BIG_F, hn = BIG_F;

    for (int idx = blockIdx.x * 256 + tid; idx < 2 * BATCH * NPTS; idx += 64 * 256) {
        int b = idx >> 13;
        int r = idx & 8191;
        float pos, mn;
        if (r < NPTS) { pos = g_pos0[b][r]; mn = g_mn0[b][r]; }
        else          { pos = g_pos1[b][r - NPTS]; mn = g_mn1[b][r - NPTS]; }
        bool valid = (pos > 0.0f) && (mn < BIG_F);
        if (valid) {
            sum += fmaxf(pos - mn + 1.0f, 0.0f);
            cnt += 1.0f;
            hp = fmaxf(hp, pos);
            hn = fminf(hn, mn);
        }
    }

    __shared__ float s_sum[8], s_cnt[8], s_hp[8], s_hn[8];
#pragma unroll
    for (int s = 16; s > 0; s >>= 1) {
        sum += __shfl_xor_sync(0xffffffffu, sum, s);
        cnt += __shfl_xor_sync(0xffffffffu, cnt, s);
        hp = fmaxf(hp, __shfl_xor_sync(0xffffffffu, hp, s));
        hn = fminf(hn, __shfl_xor_sync(0xffffffffu, hn, s));
    }
    if ((tid & 31) == 0) {
        s_sum[tid >> 5] = sum; s_cnt[tid >> 5] = cnt;
        s_hp[tid >> 5] = hp;   s_hn[tid >> 5] = hn;
    }
    __syncthreads();
    if (tid == 0) {
        sum = 0.0f; cnt = 0.0f; hp = -BIG_F; hn = BIG_F;
#pragma unroll
        for (int i = 0; i < 8; i++) {
            sum += s_sum[i]; cnt += s_cnt[i];
            hp = fmaxf(hp, s_hp[i]); hn = fminf(hn, s_hn[i]);
        }
        g_psum[blockIdx.x] = sum; g_pcnt[blockIdx.x] = cnt;
        g_php[blockIdx.x] = hp;   g_phn[blockIdx.x] = hn;
    }
}

__global__ void finalize_kernel(float* __restrict__ out) {
    const int tid = threadIdx.x;   // 32 threads
    float sum = g_psum[tid] + g_psum[tid + 32];
    float cnt = g_pcnt[tid] + g_pcnt[tid + 32];
    float hp  = fmaxf(g_php[tid], g_php[tid + 32]);
    float hn  = fminf(g_phn[tid], g_phn[tid + 32]);
#pragma unroll
    for (int s = 16; s > 0; s >>= 1) {
        sum += __shfl_xor_sync(0xffffffffu, sum, s);
        cnt += __shfl_xor_sync(0xffffffffu, cnt, s);
        hp = fmaxf(hp, __shfl_xor_sync(0xffffffffu, hp, s));
        hn = fminf(hn, __shfl_xor_sync(0xffffffffu, hn, s));
    }
    if (tid == 0) {
        out[0] = sum / fmaxf(cnt, 1.0f);
        out[1] = hp;
        out[2] = hn;
    }
}

// ---------------------------------------------------------------------------
extern "C" void kernel_launch(void* const* d_in, const int* in_sizes, int n_in,
                              void* d_out, int out_size) {
    const float* desc0 = (const float*)d_in[0];
    const float* desc1 = (const float*)d_in[1];
    const float* mat   = (const float*)d_in[2];
    float* out = (float*)d_out;

    cudaFuncSetAttribute(pass1_kernel,
                         cudaFuncAttributeMaxDynamicSharedMemorySize, P1_SMEM);

    init_kernel<<<16, 1024>>>();
    prep_kernel<<<4096, 256>>>(desc0, desc1);
    pass1_kernel<<<dim3(NPTS / 128, NPTS / 128, BATCH), 256, P1_SMEM>>>(mat);
    pass2_kernel<<<dim3(NPTS / 256, NPTS / 128, BATCH), 256>>>();
    partial_kernel<<<64, 256>>>();
    finalize_kernel<<<1, 32>>>(out);
}

// round 16
// speedup vs baseline: 1.0274x; 1.0274x over previous
#include <cuda_runtime.h>
#include <cuda_fp16.h>
#include <cstdint>

#define BATCH   4
#define DDIM    256
#define NPTS    4096
#define MSTRIDE 4097
#define MARGIN_F 0.5f
#define MAXDIST_F 10000.0f
#define BIG_F 1000000000.0f

// ---------------- scratch ----------------
__device__ __half g_negh[(size_t)BATCH * NPTS * NPTS];        // 128 MiB
__device__ float g_pos0[BATCH][NPTS];
__device__ float g_pos1[BATCH][NPTS];
__device__ float g_mn0[BATCH][NPTS];
__device__ float g_mn1[BATCH][NPTS];
// fp16 operands, (b, d, n) layout (K-major rows of n)
__device__ __half g_f0[(size_t)BATCH * DDIM * NPTS];
__device__ __half g_f1[(size_t)BATCH * DDIM * NPTS];
__device__ float g_psum[64], g_pcnt[64], g_php[64], g_phn[64];

// ---------------- ptx helpers ----------------
#define LDSM_T4(r0,r1,r2,r3, addr)                                              \
    asm volatile("ldmatrix.sync.aligned.m8n8.x4.trans.shared.b16 "              \
                 "{%0,%1,%2,%3}, [%4];"                                         \
                 : "=r"(r0), "=r"(r1), "=r"(r2), "=r"(r3) : "r"(addr))

#define MMA16816(d, a, b0, b1)                                                  \
    asm volatile("mma.sync.aligned.m16n8k16.row.col.f32.f16.f16.f32 "           \
                 "{%0,%1,%2,%3},{%4,%5,%6,%7},{%8,%9},{%0,%1,%2,%3};"           \
                 : "+f"(d[0]), "+f"(d[1]), "+f"(d[2]), "+f"(d[3])               \
                 : "r"(a[0]), "r"(a[1]), "r"(a[2]), "r"(a[3]),                  \
                   "r"(b0), "r"(b1))

#define CP_ASYNC16(sm, gm)                                                      \
    asm volatile("cp.async.cg.shared.global [%0], [%1], 16;" :: "r"(sm), "l"(gm))
#define CP_COMMIT()  asm volatile("cp.async.commit_group;")
#define CP_WAIT1()   asm volatile("cp.async.wait_group 1;")
#define CP_WAIT0()   asm volatile("cp.async.wait_group 0;")

// ---------------- init ----------------
__global__ void init_kernel() {
    int idx = blockIdx.x * blockDim.x + threadIdx.x;
    if (idx < BATCH * NPTS) {
        ((float*)g_pos0)[idx] = 0.0f;
        ((float*)g_pos1)[idx] = 0.0f;
        ((float*)g_mn0)[idx]  = BIG_F;
        ((float*)g_mn1)[idx]  = BIG_F;
    }
}

// ---------------- prep: fp32 -> fp16, same (b,d,n) layout ----------------
__global__ __launch_bounds__(256)
void prep_kernel(const float* __restrict__ d0, const float* __restrict__ d1) {
    size_t i = ((size_t)blockIdx.x * 256 + threadIdx.x) * 4;
    float4 v0 = *(const float4*)(d0 + i);
    float4 v1 = *(const float4*)(d1 + i);
    __half2 a0 = __floats2half2_rn(v0.x, v0.y);
    __half2 a1 = __floats2half2_rn(v0.z, v0.w);
    __half2 b0 = __floats2half2_rn(v1.x, v1.y);
    __half2 b1 = __floats2half2_rn(v1.z, v1.w);
    *(uint2*)(g_f0 + i) = make_uint2(*(uint32_t*)&a0, *(uint32_t*)&a1);
    *(uint2*)(g_f1 + i) = make_uint2(*(uint32_t*)&b0, *(uint32_t*)&b1);
}

// ---------------------------------------------------------------------------
// pass1: fp16 HMMA GEMM K=256, tile 128x128, 8 warps (64x32), BK=16,
// 3-stage cp.async pipeline. mat (ov) tile prefetched to smem DURING the MMA
// loop via 16B cp.async. The FULL global float index (incl. batch offset,
// 4097^2 == 1 mod 4 -> += b) is aligned down to a 16B boundary; 34 float4
// per row cover floats [0,135] of the 128-col window. Per-row data offset in
// smem = (b + i0 + row + j0) & 3.
// Fused epilogue: dist, mask row/col max atomics, fp16 neg store.
// ---------------------------------------------------------------------------
#define LDA 136
#define NCH 16     // 256 / 16
#define MROWS 140  // mat smem row stride (floats); 34*4=136 data + 4 pad
#define SM_AS 0
#define SM_BS 13056
#define SM_MV 26112
#define P1_SMEM (26112 + 128 * MROWS * 4)   // 97792

__global__ __launch_bounds__(256, 2)
void pass1_kernel(const float* __restrict__ mat) {
    extern __shared__ char smem_raw[];
    __half (*As)[16][LDA] = (__half(*)[16][LDA])(smem_raw + SM_AS);
    __half (*Bs)[16][LDA] = (__half(*)[16][LDA])(smem_raw + SM_BS);
    float*  Ms            = (float*)(smem_raw + SM_MV);

    const int b  = blockIdx.z;
    const int i0 = blockIdx.y * 128;
    const int j0 = blockIdx.x * 128;

    const int tid = threadIdx.x;
    const int w   = tid >> 5;
    const int l   = tid & 31;
    const int m0w = (w & 1) * 64;
    const int n0w = (w >> 1) * 32;

    const __half* Ag0 = g_f0 + (size_t)b * DDIM * NPTS;
    const __half* Bg0 = g_f1 + (size_t)b * DDIM * NPTS;

    const int lrow = tid >> 4;          // 0..15
    const int lcol = (tid & 15) * 8;    // half elems
    // mat loader mapping: 272 ops (8 rows x 34 float4); 16 threads do 2 ops
    const int mr1 = tid / 34, mk1 = tid % 34;
    const int mr2 = (tid + 256) / 34, mk2 = (tid + 256) % 34;
    const uint32_t ms_base = (uint32_t)__cvta_generic_to_shared(Ms);

    auto load_stage = [&](int kc) {
        int st = kc % 3;
        int kk = kc * 16;
        const __half* Ag = Ag0 + (size_t)(kk + lrow) * NPTS + i0 + lcol;
        const __half* Bg = Bg0 + (size_t)(kk + lrow) * NPTS + j0 + lcol;
        uint32_t sa = (uint32_t)__cvta_generic_to_shared(&As[st][lrow][lcol]);
        uint32_t sb = (uint32_t)__cvta_generic_to_shared(&Bs[st][lrow][lcol]);
        CP_ASYNC16(sa, Ag);
        CP_ASYNC16(sb, Bg);
        // mat rows kc*8 .. kc*8+7: align the FULL index (incl. batch) to 16B
        {
            int r = kc * 8 + mr1;
            size_t g = (size_t)b * MSTRIDE * MSTRIDE + (size_t)(i0 + r) * MSTRIDE + j0;
            const float* src = mat + (g & ~(size_t)3) + 4 * mk1;
            CP_ASYNC16(ms_base + (r * MROWS + 4 * mk1) * 4, src);
        }
        if (tid < 16) {
            int r = kc * 8 + mr2;
            size_t g = (size_t)b * MSTRIDE * MSTRIDE + (size_t)(i0 + r) * MSTRIDE + j0;
            const float* src = mat + (g & ~(size_t)3) + 4 * mk2;
            CP_ASYNC16(ms_base + (r * MROWS + 4 * mk2) * 4, src);
        }
        CP_COMMIT();
    };

    float acc[4][4][4];
#pragma unroll
    for (int mi = 0; mi < 4; mi++)
#pragma unroll
        for (int nj = 0; nj < 4; nj++)
#pragma unroll
            for (int r = 0; r < 4; r++) acc[mi][nj][r] = 0.0f;

    const int a_row = ((l >> 4) << 3) + (l & 7);
    const int a_col = ((l >> 3) & 1) * 8;
    const int b_row = (((l >> 3) & 1) << 3) + (l & 7);
    const int b_col = (l >> 4) * 8;

    load_stage(0);
    load_stage(1);

    for (int kc = 0; kc < NCH; kc++) {
        if (kc + 1 < NCH) { CP_WAIT1(); } else { CP_WAIT0(); }
        __syncthreads();
        if (kc + 2 < NCH) load_stage(kc + 2);

        const int st = kc % 3;
        uint32_t a[4][4];
#pragma unroll
        for (int mi = 0; mi < 4; mi++) {
            uint32_t addr = (uint32_t)__cvta_generic_to_shared(
                &As[st][a_row][m0w + mi * 16 + a_col]);
            LDSM_T4(a[mi][0], a[mi][1], a[mi][2], a[mi][3], addr);
        }
        uint32_t bq[2][4];
#pragma unroll
        for (int nb = 0; nb < 2; nb++) {
            uint32_t addr = (uint32_t)__cvta_generic_to_shared(
                &Bs[st][b_row][n0w + nb * 16 + b_col]);
            LDSM_T4(bq[nb][0], bq[nb][1], bq[nb][2], bq[nb][3], addr);
        }
#pragma unroll
        for (int mi = 0; mi < 4; mi++)
#pragma unroll
            for (int nj = 0; nj < 4; nj++)
                MMA16816(acc[mi][nj], a[mi], bq[nj >> 1][(nj & 1) * 2],
                         bq[nj >> 1][(nj & 1) * 2 + 1]);
    }

    // ---- epilogue (ov from smem; only neg store hits DRAM) ----
    __half* negbase = g_negh + (size_t)b * NPTS * NPTS;

    float cmax[4][2];
#pragma unroll
    for (int nj = 0; nj < 4; nj++) { cmax[nj][0] = 0.0f; cmax[nj][1] = 0.0f; }

#pragma unroll
    for (int mi = 0; mi < 4; mi++) {
#pragma unroll
        for (int h = 0; h < 2; h++) {
            const int rl = m0w + mi * 16 + (l >> 2) + h * 8;
            const int r  = i0 + rl;
            const int off = (b + i0 + rl + j0) & 3;
            const float* Mrow = Ms + rl * MROWS + off;
            __half* Nr = negbase + (size_t)r * NPTS;
            float rm = 0.0f;
#pragma unroll
            for (int nj = 0; nj < 4; nj++) {
                const int cl = n0w + nj * 8 + (l & 3) * 2;
                const int cb = j0 + cl;
                float v0 = acc[mi][nj][h * 2 + 0];
                float v1 = acc[mi][nj][h * 2 + 1];
                float dA = fmaf(-2.0f, v0, 2.0f);
                float dB = fmaf(-2.0f, v1, 2.0f);
                float ovx = Mrow[cl];
                float ovy = Mrow[cl + 1];
                if (ovx > 0.3f) { rm = fmaxf(rm, dA); cmax[nj][0] = fmaxf(cmax[nj][0], dA); }
                if (ovy > 0.3f) { rm = fmaxf(rm, dB); cmax[nj][1] = fmaxf(cmax[nj][1], dB); }
                float nA = (ovx <= 0.0f) ? dA : MAXDIST_F;
                float nB = (ovy <= 0.0f) ? dB : MAXDIST_F;
                *(__half2*)(Nr + cb) = __floats2half2_rn(nA, nB);
            }
            rm = fmaxf(rm, __shfl_xor_sync(0xffffffffu, rm, 1));
            rm = fmaxf(rm, __shfl_xor_sync(0xffffffffu, rm, 2));
            if ((l & 3) == 0)
                atomicMax((int*)&g_pos0[b][r], __float_as_int(rm));
        }
    }
#pragma unroll
    for (int nj = 0; nj < 4; nj++) {
#pragma unroll
        for (int p = 0; p < 2; p++) {
            float cm = cmax[nj][p];
            cm = fmaxf(cm, __shfl_xor_sync(0xffffffffu, cm, 4));
            cm = fmaxf(cm, __shfl_xor_sync(0xffffffffu, cm, 8));
            cm = fmaxf(cm, __shfl_xor_sync(0xffffffffu, cm, 16));
            if (l < 4)
                atomicMax((int*)&g_pos1[b][j0 + n0w + nj * 8 + (l & 3) * 2 + p],
                          __float_as_int(cm));
        }
    }
}

// ---------------------------------------------------------------------------
// pass2: masked min on fp16 neg; 128 rows x 256 cols per block,
// 16 cols/thread, half2 SIMD throughout.
// ---------------------------------------------------------------------------
__global__ __launch_bounds__(256)
void pass2_kernel() {
    const int b  = blockIdx.z;
    const int i0 = blockIdx.y * 128;
    const int j0 = blockIdx.x * 256;

    const int tid = threadIdx.x;
    const int tx = tid & 15;      // 16 threads x 16 cols = 256 cols
    const int ty = tid >> 4;      // 16 groups x 8 rows = 128 rows

    __shared__ __half2 cbuf[16][128];

    const __half* negbase = g_negh + (size_t)b * NPTS * NPTS;
    const __half2 one2 = __float2half2_rn(1.0f);
    const __half2 big2 = __float2half2_rn(30000.0f);
    const __half2 mar2 = __float2half2_rn(MARGIN_F);

    // column window bounds (8 half2 pairs covering 16 cols)
    __half2 p1lo[8], p1hi[8];
#pragma unroll
    for (int c2 = 0; c2 < 8; c2++) {
        float a = g_pos1[b][j0 + tx * 16 + 2 * c2];
        float c = g_pos1[b][j0 + tx * 16 + 2 * c2 + 1];
        p1lo[c2] = __floats2half2_rn(a, c);
        p1hi[c2] = __hadd2(p1lo[c2], mar2);
    }

    __half2 cmin2[8];
#pragma unroll
    for (int c2 = 0; c2 < 8; c2++) cmin2[c2] = big2;

#pragma unroll
    for (int r = 0; r < 8; r++) {
        const int i = i0 + ty * 8 + r;
        const float p0 = g_pos0[b][i];
        const __half2 p02  = __float2half2_rn(p0);
        const __half2 phi2 = __float2half2_rn(p0 + MARGIN_F);
        const __half* Nr = negbase + (size_t)i * NPTS + j0 + tx * 16;
        float4 raw0 = *(const float4*)Nr;
        float4 raw1 = *(const float4*)(Nr + 8);
        __half2 v[8];
        v[0] = *(__half2*)&raw0.x; v[1] = *(__half2*)&raw0.y;
        v[2] = *(__half2*)&raw0.z; v[3] = *(__half2*)&raw0.w;
        v[4] = *(__half2*)&raw1.x; v[5] = *(__half2*)&raw1.y;
        v[6] = *(__half2*)&raw1.z; v[7] = *(__half2*)&raw1.w;

        __half2 rmin2 = big2;
#pragma unroll
        for (int c2 = 0; c2 < 8; c2++) {
            __half2 ok = __hmul2(__hgt2(v[c2], p02), __hlt2(v[c2], phi2));
            rmin2 = __hmin2(rmin2, __hfma2(__hsub2(one2, ok), big2, v[c2]));

            __half2 okc = __hmul2(__hgt2(v[c2], p1lo[c2]), __hlt2(v[c2], p1hi[c2]));
            cmin2[c2] = __hmin2(cmin2[c2], __hfma2(__hsub2(one2, okc), big2, v[c2]));
        }
        // row min: reduce over the 16 tx lanes
        float m = fminf(__low2float(rmin2), __high2float(rmin2));
#pragma unroll
        for (int s = 8; s > 0; s >>= 1)
            m = fminf(m, __shfl_xor_sync(0xffffffffu, m, s));
        if (tx == 0) {
            float mv = (m < 5000.0f) ? m : BIG_F;
            atomicMin((int*)&g_mn0[b][i], __float_as_int(mv));
        }
    }

    // col min via smem (half2 lanes)
#pragma unroll
    for (int c2 = 0; c2 < 8; c2++)
        cbuf[ty][tx * 8 + c2] = cmin2[c2];
    __syncthreads();
    if (tid < 128) {
        __half2 m2 = big2;
#pragma unroll
        for (int rr = 0; rr < 16; rr++)
            m2 = __hmin2(m2, cbuf[rr][tid]);
        float mlo = __low2float(m2), mhi = __high2float(m2);
        float vlo = (mlo < 5000.0f) ? mlo : BIG_F;
        float vhi = (mhi < 5000.0f) ? mhi : BIG_F;
        atomicMin((int*)&g_mn1[b][j0 + 2 * tid],     __float_as_int(vlo));
        atomicMin((int*)&g_mn1[b][j0 + 2 * tid + 1], __float_as_int(vhi));
    }
}

// ---------------------------------------------------------------------------
// final reduction: 64-block partial + tiny finalize
// ---------------------------------------------------------------------------
__global__ __launch_bounds__(256)
void partial_kernel() {
    const int tid = threadIdx.x;
    float sum = 0.0f, cnt = 0.0f, hp = -BIG_F, hn = BIG_F;

    for (int idx = blockIdx.x * 256 + tid; idx < 2 * BATCH * NPTS; idx += 64 * 256) {
        int b = idx >> 13;
        int r = idx & 8191;
        float pos, mn;
        if (r < NPTS) { pos = g_pos0[b][r]; mn = g_mn0[b][r]; }
        else          { pos = g_pos1[b][r - NPTS]; mn = g_mn1[b][r - NPTS]; }
        bool valid = (pos > 0.0f) && (mn < BIG_F);
        if (valid) {
            sum += fmaxf(pos - mn + 1.0f, 0.0f);
            cnt += 1.0f;
            hp = fmaxf(hp, pos);
            hn = fminf(hn, mn);
        }
    }

    __shared__ float s_sum[8], s_cnt[8], s_hp[8], s_hn[8];
#pragma unroll
    for (int s = 16; s > 0; s >>= 1) {
        sum += __shfl_xor_sync(0xffffffffu, sum, s);
        cnt += __shfl_xor_sync(0xffffffffu, cnt, s);
        hp = fmaxf(hp, __shfl_xor_sync(0xffffffffu, hp, s));
        hn = fminf(hn, __shfl_xor_sync(0xffffffffu, hn, s));
    }
    if ((tid & 31) == 0) {
        s_sum[tid >> 5] = sum; s_cnt[tid >> 5] = cnt;
        s_hp[tid >> 5] = hp;   s_hn[tid >> 5] = hn;
    }
    __syncthreads();
    if (tid == 0) {
        sum = 0.0f; cnt = 0.0f; hp = -BIG_F; hn = BIG_F;
#pragma unroll
        for (int i = 0; i < 8; i++) {
            sum += s_sum[i]; cnt += s_cnt[i];
            hp = fmaxf(hp, s_hp[i]); hn = fminf(hn, s_hn[i]);
        }
        g_psum[blockIdx.x] = sum; g_pcnt[blockIdx.x] = cnt;
        g_php[blockIdx.x] = hp;   g_phn[blockIdx.x] = hn;
    }
}

__global__ void finalize_kernel(float* __restrict__ out) {
    const int tid = threadIdx.x;   // 32 threads
    float sum = g_psum[tid] + g_psum[tid + 32];
    float cnt = g_pcnt[tid] + g_pcnt[tid + 32];
    float hp  = fmaxf(g_php[tid], g_php[tid + 32]);
    float hn  = fminf(g_phn[tid], g_phn[tid + 32]);
#pragma unroll
    for (int s = 16; s > 0; s >>= 1) {
        sum += __shfl_xor_sync(0xffffffffu, sum, s);
        cnt += __shfl_xor_sync(0xffffffffu, cnt, s);
        hp = fmaxf(hp, __shfl_xor_sync(0xffffffffu, hp, s));
        hn = fminf(hn, __shfl_xor_sync(0xffffffffu, hn, s));
    }
    if (tid == 0) {
        out[0] = sum / fmaxf(cnt, 1.0f);
        out[1] = hp;
        out[2] = hn;
    }
}

// ---------------------------------------------------------------------------
extern "C" void kernel_launch(void* const* d_in, const int* in_sizes, int n_in,
                              void* d_out, int out_size) {
    const float* desc0 = (const float*)d_in[0];
    const float* desc1 = (const float*)d_in[1];
    const float* mat   = (const float*)d_in[2];
    float* out = (float*)d_out;

    cudaFuncSetAttribute(pass1_kernel,
                         cudaFuncAttributeMaxDynamicSharedMemorySize, P1_SMEM);

    init_kernel<<<16, 1024>>>();
    prep_kernel<<<4096, 256>>>(desc0, desc1);
    pass1_kernel<<<dim3(NPTS / 128, NPTS / 128, BATCH), 256, P1_SMEM>>>(mat);
    pass2_kernel<<<dim3(NPTS / 256, NPTS / 128, BATCH), 256>>>();
    partial_kernel<<<64, 256>>>();
    finalize_kernel<<<1, 32>>>(out);
}

// round 17
// speedup vs baseline: 1.1271x; 1.0971x over previous
#include <cuda_runtime.h>
#include <cuda_fp16.h>
#include <cstdint>

#define BATCH   4
#define DDIM    256
#define NPTS    4096
#define MSTRIDE 4097
#define MARGIN_F 0.5f
#define MAXDIST_F 10000.0f
#define BIG_F 1000000000.0f

// ---------------- scratch ----------------
__device__ __half g_negh[(size_t)BATCH * NPTS * NPTS];        // 128 MiB
__device__ float g_pos0[BATCH][NPTS];
__device__ float g_pos1[BATCH][NPTS];
__device__ float g_mn0[BATCH][NPTS];
__device__ float g_mn1[BATCH][NPTS];
// fp16 operands, (b, d, n) layout (K-major rows of n)
__device__ __half g_f0[(size_t)BATCH * DDIM * NPTS];
__device__ __half g_f1[(size_t)BATCH * DDIM * NPTS];
__device__ float g_psum[64], g_pcnt[64], g_php[64], g_phn[64];

// ---------------- ptx helpers ----------------
#define LDSM_T4(r0,r1,r2,r3, addr)                                              \
    asm volatile("ldmatrix.sync.aligned.m8n8.x4.trans.shared.b16 "              \
                 "{%0,%1,%2,%3}, [%4];"                                         \
                 : "=r"(r0), "=r"(r1), "=r"(r2), "=r"(r3) : "r"(addr))

#define MMA16816(d, a, b0, b1)                                                  \
    asm volatile("mma.sync.aligned.m16n8k16.row.col.f32.f16.f16.f32 "           \
                 "{%0,%1,%2,%3},{%4,%5,%6,%7},{%8,%9},{%0,%1,%2,%3};"           \
                 : "+f"(d[0]), "+f"(d[1]), "+f"(d[2]), "+f"(d[3])               \
                 : "r"(a[0]), "r"(a[1]), "r"(a[2]), "r"(a[3]),                  \
                   "r"(b0), "r"(b1))

#define CP_ASYNC16(sm, gm)                                                      \
    asm volatile("cp.async.cg.shared.global [%0], [%1], 16;" :: "r"(sm), "l"(gm))
#define CP_COMMIT()  asm volatile("cp.async.commit_group;")
#define CP_WAIT1()   asm volatile("cp.async.wait_group 1;")
#define CP_WAIT0()   asm volatile("cp.async.wait_group 0;")

// ---------------- init ----------------
__global__ void init_kernel() {
    int idx = blockIdx.x * blockDim.x + threadIdx.x;
    if (idx < BATCH * NPTS) {
        ((float*)g_pos0)[idx] = 0.0f;
        ((float*)g_pos1)[idx] = 0.0f;
        ((float*)g_mn0)[idx]  = BIG_F;
        ((float*)g_mn1)[idx]  = BIG_F;
    }
}

// ---------------- prep: fp32 -> fp16, same (b,d,n) layout ----------------
__global__ __launch_bounds__(256)
void prep_kernel(const float* __restrict__ d0, const float* __restrict__ d1) {
    size_t i = ((size_t)blockIdx.x * 256 + threadIdx.x) * 4;
    float4 v0 = *(const float4*)(d0 + i);
    float4 v1 = *(const float4*)(d1 + i);
    __half2 a0 = __floats2half2_rn(v0.x, v0.y);
    __half2 a1 = __floats2half2_rn(v0.z, v0.w);
    __half2 b0 = __floats2half2_rn(v1.x, v1.y);
    __half2 b1 = __floats2half2_rn(v1.z, v1.w);
    *(uint2*)(g_f0 + i) = make_uint2(*(uint32_t*)&a0, *(uint32_t*)&a1);
    *(uint2*)(g_f1 + i) = make_uint2(*(uint32_t*)&b0, *(uint32_t*)&b1);
}

// ---------------------------------------------------------------------------
// pass1: fp16 HMMA GEMM K=256, tile 128x128, 8 warps (64x32), BK=32,
// 8 chunks, 3-stage cp.async pipeline (fewer syncs, longer MMA runs per
// chunk to amortize per-chunk fixed costs). Epilogue: dist, mask row/col max
// atomics (mat via __ldg), fp16 neg store.
// ---------------------------------------------------------------------------
#define LDA 136
#define NCH 8            // 256 / 32
#define TILE_B (32 * LDA * 2)          // 8704 bytes per matrix per stage
#define P1_SMEM (6 * TILE_B)           // 52224

__global__ __launch_bounds__(256, 2)
void pass1_kernel(const float* __restrict__ mat) {
    extern __shared__ char smem_raw[];
    __half (*As)[32][LDA] = (__half(*)[32][LDA])(smem_raw);
    __half (*Bs)[32][LDA] = (__half(*)[32][LDA])(smem_raw + 3 * TILE_B);

    const int b  = blockIdx.z;
    const int i0 = blockIdx.y * 128;
    const int j0 = blockIdx.x * 128;

    const int tid = threadIdx.x;
    const int w   = tid >> 5;
    const int l   = tid & 31;
    const int m0w = (w & 1) * 64;
    const int n0w = (w >> 1) * 32;

    const __half* Ag0 = g_f0 + (size_t)b * DDIM * NPTS;
    const __half* Bg0 = g_f1 + (size_t)b * DDIM * NPTS;

    const int lrow = tid >> 4;          // 0..15
    const int lcol = (tid & 15) * 8;    // half elems

    auto load_stage = [&](int kc) {
        int st = kc % 3;
        int kk = kc * 32;
#pragma unroll
        for (int h = 0; h < 2; h++) {
            int r = lrow + 16 * h;
            const __half* Ag = Ag0 + (size_t)(kk + r) * NPTS + i0 + lcol;
            const __half* Bg = Bg0 + (size_t)(kk + r) * NPTS + j0 + lcol;
            uint32_t sa = (uint32_t)__cvta_generic_to_shared(&As[st][r][lcol]);
            uint32_t sb = (uint32_t)__cvta_generic_to_shared(&Bs[st][r][lcol]);
            CP_ASYNC16(sa, Ag);
            CP_ASYNC16(sb, Bg);
        }
        CP_COMMIT();
    };

    float acc[4][4][4];
#pragma unroll
    for (int mi = 0; mi < 4; mi++)
#pragma unroll
        for (int nj = 0; nj < 4; nj++)
#pragma unroll
            for (int r = 0; r < 4; r++) acc[mi][nj][r] = 0.0f;

    const int a_row = ((l >> 4) << 3) + (l & 7);
    const int a_col = ((l >> 3) & 1) * 8;
    const int b_row = (((l >> 3) & 1) << 3) + (l & 7);
    const int b_col = (l >> 4) * 8;

    load_stage(0);
    load_stage(1);

    for (int kc = 0; kc < NCH; kc++) {
        if (kc + 1 < NCH) { CP_WAIT1(); } else { CP_WAIT0(); }
        __syncthreads();
        if (kc + 2 < NCH) load_stage(kc + 2);

        const int st = kc % 3;
#pragma unroll
        for (int ks = 0; ks < 2; ks++) {
            uint32_t a[4][4];
#pragma unroll
            for (int mi = 0; mi < 4; mi++) {
                uint32_t addr = (uint32_t)__cvta_generic_to_shared(
                    &As[st][ks * 16 + a_row][m0w + mi * 16 + a_col]);
                LDSM_T4(a[mi][0], a[mi][1], a[mi][2], a[mi][3], addr);
            }
            uint32_t bq[2][4];
#pragma unroll
            for (int nb = 0; nb < 2; nb++) {
                uint32_t addr = (uint32_t)__cvta_generic_to_shared(
                    &Bs[st][ks * 16 + b_row][n0w + nb * 16 + b_col]);
                LDSM_T4(bq[nb][0], bq[nb][1], bq[nb][2], bq[nb][3], addr);
            }
#pragma unroll
            for (int mi = 0; mi < 4; mi++)
#pragma unroll
                for (int nj = 0; nj < 4; nj++)
                    MMA16816(acc[mi][nj], a[mi], bq[nj >> 1][(nj & 1) * 2],
                             bq[nj >> 1][(nj & 1) * 2 + 1]);
        }
    }

    // ---- epilogue (round-9 proven: mat via __ldg, fp16 neg store) ----
    const float* Mbase   = mat + (size_t)b * MSTRIDE * MSTRIDE;
    __half*      negbase = g_negh + (size_t)b * NPTS * NPTS;

    float cmax[4][2];
#pragma unroll
    for (int nj = 0; nj < 4; nj++) { cmax[nj][0] = 0.0f; cmax[nj][1] = 0.0f; }

#pragma unroll
    for (int mi = 0; mi < 4; mi++) {
#pragma unroll
        for (int h = 0; h < 2; h++) {
            const int r = i0 + m0w + mi * 16 + (l >> 2) + h * 8;
            const float* Mr = Mbase + (size_t)r * MSTRIDE;
            __half* Nr = negbase + (size_t)r * NPTS;
            float rm = 0.0f;
#pragma unroll
            for (int nj = 0; nj < 4; nj++) {
                const int cb = j0 + n0w + nj * 8 + (l & 3) * 2;
                float v0 = acc[mi][nj][h * 2 + 0];
                float v1 = acc[mi][nj][h * 2 + 1];
                float dA = fmaf(-2.0f, v0, 2.0f);
                float dB = fmaf(-2.0f, v1, 2.0f);
                float ovA = __ldg(Mr + cb);
                float ovB = __ldg(Mr + cb + 1);
                if (ovA > 0.3f) { rm = fmaxf(rm, dA); cmax[nj][0] = fmaxf(cmax[nj][0], dA); }
                if (ovB > 0.3f) { rm = fmaxf(rm, dB); cmax[nj][1] = fmaxf(cmax[nj][1], dB); }
                float nA = (ovA <= 0.0f) ? dA : MAXDIST_F;
                float nB = (ovB <= 0.0f) ? dB : MAXDIST_F;
                *(__half2*)(Nr + cb) = __floats2half2_rn(nA, nB);
            }
            rm = fmaxf(rm, __shfl_xor_sync(0xffffffffu, rm, 1));
            rm = fmaxf(rm, __shfl_xor_sync(0xffffffffu, rm, 2));
            if ((l & 3) == 0)
                atomicMax((int*)&g_pos0[b][r], __float_as_int(rm));
        }
    }
#pragma unroll
    for (int nj = 0; nj < 4; nj++) {
#pragma unroll
        for (int p = 0; p < 2; p++) {
            float cm = cmax[nj][p];
            cm = fmaxf(cm, __shfl_xor_sync(0xffffffffu, cm, 4));
            cm = fmaxf(cm, __shfl_xor_sync(0xffffffffu, cm, 8));
            cm = fmaxf(cm, __shfl_xor_sync(0xffffffffu, cm, 16));
            if (l < 4)
                atomicMax((int*)&g_pos1[b][j0 + n0w + nj * 8 + (l & 3) * 2 + p],
                          __float_as_int(cm));
        }
    }
}

// ---------------------------------------------------------------------------
// pass2: masked min on fp16 neg; 128 rows x 256 cols per block, 16 cols/
// thread. Row reductions HOISTED out of the load loop so the 16 float4
// loads batch (MLP), instead of being fenced by shfl chains per row.
// ---------------------------------------------------------------------------
__global__ __launch_bounds__(256)
void pass2_kernel() {
    const int b  = blockIdx.z;
    const int i0 = blockIdx.y * 128;
    const int j0 = blockIdx.x * 256;

    const int tid = threadIdx.x;
    const int tx = tid & 15;      // 16 threads x 16 cols = 256 cols
    const int ty = tid >> 4;      // 16 groups x 8 rows = 128 rows

    __shared__ __half2 cbuf[16][128];

    const __half* negbase = g_negh + (size_t)b * NPTS * NPTS;
    const __half2 one2 = __float2half2_rn(1.0f);
    const __half2 big2 = __float2half2_rn(30000.0f);
    const __half2 mar2 = __float2half2_rn(MARGIN_F);

    // column window bounds (8 half2 pairs covering 16 cols)
    __half2 p1lo[8], p1hi[8];
#pragma unroll
    for (int c2 = 0; c2 < 8; c2++) {
        float a = g_pos1[b][j0 + tx * 16 + 2 * c2];
        float c = g_pos1[b][j0 + tx * 16 + 2 * c2 + 1];
        p1lo[c2] = __floats2half2_rn(a, c);
        p1hi[c2] = __hadd2(p1lo[c2], mar2);
    }

    __half2 cmin2[8], rmin2[8];
#pragma unroll
    for (int c2 = 0; c2 < 8; c2++) cmin2[c2] = big2;
#pragma unroll
    for (int r = 0; r < 8; r++) rmin2[r] = big2;

#pragma unroll
    for (int r = 0; r < 8; r++) {
        const int i = i0 + ty * 8 + r;
        const float p0 = g_pos0[b][i];
        const __half2 p02  = __float2half2_rn(p0);
        const __half2 phi2 = __float2half2_rn(p0 + MARGIN_F);
        const __half* Nr = negbase + (size_t)i * NPTS + j0 + tx * 16;
        float4 raw0 = *(const float4*)Nr;
        float4 raw1 = *(const float4*)(Nr + 8);
        __half2 v[8];
        v[0] = *(__half2*)&raw0.x; v[1] = *(__half2*)&raw0.y;
        v[2] = *(__half2*)&raw0.z; v[3] = *(__half2*)&raw0.w;
        v[4] = *(__half2*)&raw1.x; v[5] = *(__half2*)&raw1.y;
        v[6] = *(__half2*)&raw1.z; v[7] = *(__half2*)&raw1.w;

#pragma unroll
        for (int c2 = 0; c2 < 8; c2++) {
            __half2 ok = __hmul2(__hgt2(v[c2], p02), __hlt2(v[c2], phi2));
            rmin2[r] = __hmin2(rmin2[r], __hfma2(__hsub2(one2, ok), big2, v[c2]));

            __half2 okc = __hmul2(__hgt2(v[c2], p1lo[c2]), __hlt2(v[c2], p1hi[c2]));
            cmin2[c2] = __hmin2(cmin2[c2], __hfma2(__hsub2(one2, okc), big2, v[c2]));
        }
    }

    // row mins: 8 independent shfl chains, pipelined
    float rmf[8];
#pragma unroll
    for (int r = 0; r < 8; r++)
        rmf[r] = fminf(__low2float(rmin2[r]), __high2float(rmin2[r]));
#pragma unroll
    for (int s = 8; s > 0; s >>= 1)
#pragma unroll
        for (int r = 0; r < 8; r++)
            rmf[r] = fminf(rmf[r], __shfl_xor_sync(0xffffffffu, rmf[r], s));
    if (tx == 0) {
#pragma unroll
        for (int r = 0; r < 8; r++) {
            float mv = (rmf[r] < 5000.0f) ? rmf[r] : BIG_F;
            atomicMin((int*)&g_mn0[b][i0 + ty * 8 + r], __float_as_int(mv));
        }
    }

    // col min via smem (half2 lanes)
#pragma unroll
    for (int c2 = 0; c2 < 8; c2++)
        cbuf[ty][tx * 8 + c2] = cmin2[c2];
    __syncthreads();
    if (tid < 128) {
        __half2 m2 = big2;
#pragma unroll
        for (int rr = 0; rr < 16; rr++)
            m2 = __hmin2(m2, cbuf[rr][tid]);
        float mlo = __low2float(m2), mhi = __high2float(m2);
        float vlo = (mlo < 5000.0f) ? mlo : BIG_F;
        float vhi = (mhi < 5000.0f) ? mhi : BIG_F;
        atomicMin((int*)&g_mn1[b][j0 + 2 * tid],     __float_as_int(vlo));
        atomicMin((int*)&g_mn1[b][j0 + 2 * tid + 1], __float_as_int(vhi));
    }
}

// ---------------------------------------------------------------------------
// final reduction: 64-block partial + tiny finalize
// ---------------------------------------------------------------------------
__global__ __launch_bounds__(256)
void partial_kernel() {
    const int tid = threadIdx.x;
    float sum = 0.0f, cnt = 0.0f, hp = -BIG_F, hn = BIG_F;

    for (int idx = blockIdx.x * 256 + tid; idx < 2 * BATCH * NPTS; idx += 64 * 256) {
        int b = idx >> 13;
        int r = idx & 8191;
        float pos, mn;
        if (r < NPTS) { pos = g_pos0[b][r]; mn = g_mn0[b][r]; }
        else          { pos = g_pos1[b][r - NPTS]; mn = g_mn1[b][r - NPTS]; }
        bool valid = (pos > 0.0f) && (mn < BIG_F);
        if (valid) {
            sum += fmaxf(pos - mn + 1.0f, 0.0f);
            cnt += 1.0f;
            hp = fmaxf(hp, pos);
            hn = fminf(hn, mn);
        }
    }

    __shared__ float s_sum[8], s_cnt[8], s_hp[8], s_hn[8];
#pragma unroll
    for (int s = 16; s > 0; s >>= 1) {
        sum += __shfl_xor_sync(0xffffffffu, sum, s);
        cnt += __shfl_xor_sync(0xffffffffu, cnt, s);
        hp = fmaxf(hp, __shfl_xor_sync(0xffffffffu, hp, s));
        hn = fminf(hn, __shfl_xor_sync(0xffffffffu, hn, s));
    }
    if ((tid & 31) == 0) {
        s_sum[tid >> 5] = sum; s_cnt[tid >> 5] = cnt;
        s_hp[tid >> 5] = hp;   s_hn[tid >> 5] = hn;
    }
    __syncthreads();
    if (tid == 0) {
        sum = 0.0f; cnt = 0.0f; hp = -BIG_F; hn = BIG_F;
#pragma unroll
        for (int i = 0; i < 8; i++) {
            sum += s_sum[i]; cnt += s_cnt[i];
            hp = fmaxf(hp, s_hp[i]); hn = fminf(hn, s_hn[i]);
        }
        g_psum[blockIdx.x] = sum; g_pcnt[blockIdx.x] = cnt;
        g_php[blockIdx.x] = hp;   g_phn[blockIdx.x] = hn;
    }
}

__global__ void finalize_kernel(float* __restrict__ out) {
    const int tid = threadIdx.x;   // 32 threads
    float sum = g_psum[tid] + g_psum[tid + 32];
    float cnt = g_pcnt[tid] + g_pcnt[tid + 32];
    float hp  = fmaxf(g_php[tid], g_php[tid + 32]);
    float hn  = fminf(g_phn[tid], g_phn[tid + 32]);
#pragma unroll
    for (int s = 16; s > 0; s >>= 1) {
        sum += __shfl_xor_sync(0xffffffffu, sum, s);
        cnt += __shfl_xor_sync(0xffffffffu, cnt, s);
        hp = fmaxf(hp, __shfl_xor_sync(0xffffffffu, hp, s));
        hn = fminf(hn, __shfl_xor_sync(0xffffffffu, hn, s));
    }
    if (tid == 0) {
        out[0] = sum / fmaxf(cnt, 1.0f);
        out[1] = hp;
        out[2] = hn;
    }
}

// ---------------------------------------------------------------------------
extern "C" void kernel_launch(void* const* d_in, const int* in_sizes, int n_in,
                              void* d_out, int out_size) {
    const float* desc0 = (const float*)d_in[0];
    const float* desc1 = (const float*)d_in[1];
    const float* mat   = (const float*)d_in[2];
    float* out = (float*)d_out;

    cudaFuncSetAttribute(pass1_kernel,
                         cudaFuncAttributeMaxDynamicSharedMemorySize, P1_SMEM);

    init_kernel<<<16, 1024>>>();
    prep_kernel<<<4096, 256>>>(desc0, desc1);
    pass1_kernel<<<dim3(NPTS / 128, NPTS / 128, BATCH), 256, P1_SMEM>>>(mat);
    pass2_kernel<<<dim3(NPTS / 256, NPTS / 128, BATCH), 256>>>();
    partial_kernel<<<64, 256>>>();
    finalize_kernel<<<1, 32>>>(out);
}